// round 2
// baseline (speedup 1.0000x reference)
#include <cuda_runtime.h>
#include <math.h>

// Problem constants
constexpr int NB  = 2;     // batch
constexpr int IC  = 64;    // input channels
constexpr int OC  = 64;    // output channels per branch
constexpr int IH  = 80;
constexpr int IW  = 80;
constexpr int IHW = IH * IW;   // 6400

// Scratch (sized for k=7 branch, reused sequentially per branch)
__device__ float g_off[NB * 98 * IHW];   // [b][2*KK][H][W]
__device__ float g_msk[NB * 49 * IHW];   // [b][KK][H][W]
__device__ float g_wt [49 * 64 * 64];    // [kk][c][o]

// ---------------------------------------------------------------------------
// Stage 1: fused offset + mask conv (direct conv, 16x16 tile, 8 co per block)
// grid: (W/16, (H/16) * nGroups, B), block: 256 (16x16)
// ---------------------------------------------------------------------------
template<int K>
__global__ void __launch_bounds__(256) conv_offmask(
    const float* __restrict__ x,
    const float* __restrict__ w_off, const float* __restrict__ b_off,
    const float* __restrict__ w_msk, const float* __restrict__ b_msk)
{
    constexpr int KK  = K * K;
    constexpr int PAD = K / 2;
    constexpr int CO_TOT = 3 * KK;     // 2*KK offset + KK mask channels
    constexpr int TS  = 16 + K - 1;

    __shared__ float sx[TS * TS];
    __shared__ __align__(16) float sw[KK * 8];   // [tap][co_local]

    const int tid = threadIdx.x;
    const int tx  = tid & 15;
    const int ty  = tid >> 4;
    const int bx0 = blockIdx.x * 16;
    const int by0 = (blockIdx.y % (IH / 16)) * 16;
    const int grp = blockIdx.y / (IH / 16);
    const int b   = blockIdx.z;
    const int co0 = grp * 8;

    float acc[8];
    #pragma unroll
    for (int i = 0; i < 8; i++) acc[i] = 0.f;

    for (int ci = 0; ci < IC; ci++) {
        const float* xp = x + (b * IC + ci) * IHW;
        // load x tile with halo (zero pad)
        for (int i = tid; i < TS * TS; i += 256) {
            int ry = i / TS, rx = i - ry * TS;
            int gy = by0 - PAD + ry, gx = bx0 - PAD + rx;
            float v = 0.f;
            if (gy >= 0 && gy < IH && gx >= 0 && gx < IW) v = xp[gy * IW + gx];
            sx[i] = v;
        }
        // load transposed weight slice [tap][co_local]
        for (int i = tid; i < KK * 8; i += 256) {
            int tap = i >> 3, lc = i & 7;
            int co = co0 + lc;
            float v = 0.f;
            if (co < 2 * KK)          v = w_off[(co * IC + ci) * KK + tap];
            else if (co < CO_TOT)     v = w_msk[((co - 2 * KK) * IC + ci) * KK + tap];
            sw[i] = v;
        }
        __syncthreads();

        #pragma unroll
        for (int tap = 0; tap < KK; tap++) {
            const int dy = tap / K, dx = tap - dy * K;
            const float xv = sx[(ty + dy) * TS + tx + dx];
            #pragma unroll
            for (int lc = 0; lc < 8; lc++)
                acc[lc] += xv * sw[tap * 8 + lc];
        }
        __syncthreads();
    }

    const int oy = by0 + ty, ox = bx0 + tx;
    #pragma unroll
    for (int lc = 0; lc < 8; lc++) {
        const int co = co0 + lc;
        if (co < 2 * KK) {
            g_off[(b * 2 * KK + co) * IHW + oy * IW + ox] = acc[lc] + b_off[co];
        } else if (co < CO_TOT) {
            const int cm = co - 2 * KK;
            float z = acc[lc] + b_msk[cm];
            g_msk[(b * KK + cm) * IHW + oy * IW + ox] = 1.f / (1.f + expf(-z));
        }
    }
}

// ---------------------------------------------------------------------------
// Weight transpose: w_dcn[o][c][kk] -> g_wt[kk][c][o]
// ---------------------------------------------------------------------------
template<int K>
__global__ void wt_transpose(const float* __restrict__ w_dcn)
{
    constexpr int KK = K * K;
    int i = blockIdx.x * 256 + threadIdx.x;
    if (i < KK * 64 * 64) {
        int kk = i >> 12;          // /4096
        int r  = i & 4095;
        int c  = r >> 6;
        int oo = r & 63;
        g_wt[i] = w_dcn[(oo * 64 + c) * KK + kk];
    }
}

// ---------------------------------------------------------------------------
// Stage 2: fused deformable sample + per-tap 64x64 matvec
// 32 pixels per block, 256 threads. grid: (B*H*W/32)
// ---------------------------------------------------------------------------
template<int K>
__global__ void __launch_bounds__(256) dcn_sample(
    const float* __restrict__ x,
    float* __restrict__ out, int ch_base)
{
    constexpr int KK  = K * K;
    constexpr int PAD = K / 2;
    constexpr int SP_PITCH = 68;  // samp row pitch (multiple of 4 for float4)

    __shared__ __align__(16) float s_w[64 * 64];          // [c][o]
    __shared__ __align__(16) float s_samp[32 * SP_PITCH]; // [p][c]
    __shared__ float s_py[32], s_px[32], s_m[32];

    const int tid  = threadIdx.x;
    const int pix0 = blockIdx.x * 32;
    const int b    = pix0 / IHW;
    const int rem0 = pix0 - b * IHW;

    const int o  = tid & 63;   // output channel (matvec)
    const int pg = tid >> 6;   // pixel-group 0..3 (matvec)
    const int sp = tid & 31;   // pixel (sampling)
    const int sc = tid >> 5;   // channel base 0..7 (sampling)

    float acc[8];
    #pragma unroll
    for (int i = 0; i < 8; i++) acc[i] = 0.f;

    for (int kk = 0; kk < KK; kk++) {
        // per-pixel coordinates + mask
        if (tid < 32) {
            int rem = rem0 + tid;
            int h = rem / IW, w = rem - h * IW;
            float oy = g_off[(b * 2 * KK + 2 * kk    ) * IHW + rem];
            float ox = g_off[(b * 2 * KK + 2 * kk + 1) * IHW + rem];
            s_py[tid] = (float)(h - PAD + kk / K) + oy;
            s_px[tid] = (float)(w - PAD + kk % K) + ox;
            s_m[tid]  = g_msk[(b * KK + kk) * IHW + rem];
        }
        // weight slice for this tap: contiguous 16KB
        for (int i = tid; i < 4096; i += 256)
            s_w[i] = g_wt[kk * 4096 + i];
        __syncthreads();

        // bilinear gather: each thread does pixel sp, channels sc+8j
        {
            const float py = s_py[sp], px = s_px[sp], m = s_m[sp];
            const float y0f = floorf(py), x0f = floorf(px);
            const int   y0  = (int)y0f,   x0  = (int)x0f;
            const float wy1 = py - y0f, wx1 = px - x0f;
            const float wy0 = 1.f - wy1, wx0 = 1.f - wx1;
            const bool vy0 = (y0 >= 0) && (y0 < IH);
            const bool vy1 = (y0 + 1 >= 0) && (y0 + 1 < IH);
            const bool vx0 = (x0 >= 0) && (x0 < IW);
            const bool vx1 = (x0 + 1 >= 0) && (x0 + 1 < IW);
            const int y0c = min(max(y0, 0), IH - 1);
            const int y1c = min(max(y0 + 1, 0), IH - 1);
            const int x0c = min(max(x0, 0), IW - 1);
            const int x1c = min(max(x0 + 1, 0), IW - 1);
            const float w00 = wy0 * wx0 * ((vy0 && vx0) ? 1.f : 0.f);
            const float w01 = wy0 * wx1 * ((vy0 && vx1) ? 1.f : 0.f);
            const float w10 = wy1 * wx0 * ((vy1 && vx0) ? 1.f : 0.f);
            const float w11 = wy1 * wx1 * ((vy1 && vx1) ? 1.f : 0.f);
            const int i00 = y0c * IW + x0c, i01 = y0c * IW + x1c;
            const int i10 = y1c * IW + x0c, i11 = y1c * IW + x1c;
            #pragma unroll
            for (int j = 0; j < 8; j++) {
                const int c = sc + 8 * j;
                const float* xp = x + (b * IC + c) * IHW;
                float v = w00 * xp[i00] + w01 * xp[i01]
                        + w10 * xp[i10] + w11 * xp[i11];
                s_samp[sp * SP_PITCH + c] = v * m;
            }
        }
        __syncthreads();

        // matvec: acc[jj] over 8 pixels, channel o, sum over 64 c
        #pragma unroll 4
        for (int c = 0; c < 64; c += 4) {
            const float w0 = s_w[(c + 0) * 64 + o];
            const float w1 = s_w[(c + 1) * 64 + o];
            const float w2 = s_w[(c + 2) * 64 + o];
            const float w3 = s_w[(c + 3) * 64 + o];
            #pragma unroll
            for (int jj = 0; jj < 8; jj++) {
                const int p = pg + 4 * jj;
                const float4 sv = *reinterpret_cast<const float4*>(&s_samp[p * SP_PITCH + c]);
                acc[jj] += sv.x * w0 + sv.y * w1 + sv.z * w2 + sv.w * w3;
            }
        }
        __syncthreads();
    }

    // stage through smem for coalesced global stores (stride 33: conflict-free)
    #pragma unroll
    for (int jj = 0; jj < 8; jj++) {
        const int p = pg + 4 * jj;
        s_w[o * 33 + p] = acc[jj];
    }
    __syncthreads();
    for (int i = tid; i < 2048; i += 256) {
        const int oo = i >> 5, p = i & 31;
        out[(b * 192 + ch_base + oo) * IHW + rem0 + p] = s_w[oo * 33 + p];
    }
}

// ---------------------------------------------------------------------------
// Launch: per branch: conv -> transpose -> sample (stream-serial reuse of scratch)
// Inputs: 0:x, then per k in {3,5,7}: w_off, b_off, w_mask, b_mask, w_dcn
// ---------------------------------------------------------------------------
extern "C" void kernel_launch(void* const* d_in, const int* in_sizes, int n_in,
                              void* d_out, int out_size)
{
    const float* x = (const float*)d_in[0];
    float* out = (float*)d_out;

    // k = 3: CO_TOT=27 -> 4 groups
    {
        dim3 g(IW / 16, (IH / 16) * 4, NB);
        conv_offmask<3><<<g, 256>>>(x,
            (const float*)d_in[1], (const float*)d_in[2],
            (const float*)d_in[3], (const float*)d_in[4]);
        wt_transpose<3><<<(9 * 4096 + 255) / 256, 256>>>((const float*)d_in[5]);
        dcn_sample<3><<<NB * IHW / 32, 256>>>(x, out, 0);
    }
    // k = 5: CO_TOT=75 -> 10 groups
    {
        dim3 g(IW / 16, (IH / 16) * 10, NB);
        conv_offmask<5><<<g, 256>>>(x,
            (const float*)d_in[6], (const float*)d_in[7],
            (const float*)d_in[8], (const float*)d_in[9]);
        wt_transpose<5><<<(25 * 4096 + 255) / 256, 256>>>((const float*)d_in[10]);
        dcn_sample<5><<<NB * IHW / 32, 256>>>(x, out, 64);
    }
    // k = 7: CO_TOT=147 -> 19 groups
    {
        dim3 g(IW / 16, (IH / 16) * 19, NB);
        conv_offmask<7><<<g, 256>>>(x,
            (const float*)d_in[11], (const float*)d_in[12],
            (const float*)d_in[13], (const float*)d_in[14]);
        wt_transpose<7><<<(49 * 4096 + 255) / 256, 256>>>((const float*)d_in[15]);
        dcn_sample<7><<<NB * IHW / 32, 256>>>(x, out, 128);
    }
}

// round 4
// speedup vs baseline: 1.1022x; 1.1022x over previous
#include <cuda_runtime.h>
#include <math.h>

constexpr int NB  = 2;
constexpr int IC  = 64;
constexpr int IH  = 80;
constexpr int IW  = 80;
constexpr int IHW = IH * IW;   // 6400

// Per-branch scratch
__device__ float g_off3[NB * 18 * IHW];
__device__ float g_msk3[NB *  9 * IHW];
__device__ float g_wt3 [ 9 * 4096];
__device__ float g_off5[NB * 50 * IHW];
__device__ float g_msk5[NB * 25 * IHW];
__device__ float g_wt5 [25 * 4096];
__device__ float g_off7[NB * 98 * IHW];
__device__ float g_msk7[NB * 49 * IHW];
__device__ float g_wt7 [49 * 4096];

// ---- f32x2 packed helpers (sm_103a) ----
using u64 = unsigned long long;
__device__ __forceinline__ u64 pack2(float a, float b) {
    u64 r; asm("mov.b64 %0, {%1, %2};" : "=l"(r) : "f"(a), "f"(b)); return r;
}
__device__ __forceinline__ void ffma2(u64& d, u64 a, u64 b) {
    asm("fma.rn.f32x2 %0, %1, %2, %3;" : "=l"(d) : "l"(a), "l"(b), "l"(d));
}
__device__ __forceinline__ float2 unpack2(u64 v) {
    float x, y; asm("mov.b64 {%0, %1}, %2;" : "=f"(x), "=f"(y) : "l"(v));
    return make_float2(x, y);
}

// ---------------------------------------------------------------------------
// Fused offset+mask conv. 16x16 spatial tile, 128 threads (16x8), each thread
// 2 pixels (ty, ty+8) x 16 output channels (as 8 f32x2 pairs).
// grid: (5, 5*NG, NB)
// ---------------------------------------------------------------------------
template<int K, int NG>
__global__ void __launch_bounds__(128) conv_offmask(
    const float* __restrict__ x,
    const float* __restrict__ w_off, const float* __restrict__ b_off,
    const float* __restrict__ w_msk, const float* __restrict__ b_msk)
{
    constexpr int KK  = K * K;
    constexpr int PAD = K / 2;
    constexpr int CO_TOT = 3 * KK;
    constexpr int TS  = 16 + K - 1;
    constexpr int P   = TS | 1;          // odd pitch: conflict-free dual-row LDS

    float* offp = (K == 3) ? g_off3 : (K == 5) ? g_off5 : g_off7;
    float* mskp = (K == 3) ? g_msk3 : (K == 5) ? g_msk5 : g_msk7;

    __shared__ float sx[TS * P];
    __shared__ __align__(16) float sw[KK * 16];   // [tap][16 co]

    const int tid = threadIdx.x;
    const int tx  = tid & 15;
    const int ty  = tid >> 4;            // 0..7
    const int bx0 = blockIdx.x * 16;
    const int by0 = (blockIdx.y % 5) * 16;
    const int grp = blockIdx.y / 5;
    const int b   = blockIdx.z;
    const int co0 = grp * 16;

    u64 acc0[8], acc1[8];
    #pragma unroll
    for (int i = 0; i < 8; i++) { acc0[i] = 0ull; acc1[i] = 0ull; }

    for (int ci = 0; ci < IC; ci++) {
        const float* xp = x + (b * IC + ci) * IHW;
        for (int i = tid; i < TS * TS; i += 128) {
            int ry = i / TS, rx = i - ry * TS;
            int gy = by0 - PAD + ry, gx = bx0 - PAD + rx;
            float v = 0.f;
            if (gy >= 0 && gy < IH && gx >= 0 && gx < IW) v = xp[gy * IW + gx];
            sx[ry * P + rx] = v;
        }
        for (int i = tid; i < 16 * KK; i += 128) {
            int lc = i / KK, tap = i - lc * KK;
            int co = co0 + lc;
            float v = 0.f;
            if (co < 2 * KK)       v = w_off[(co * IC + ci) * KK + tap];
            else if (co < CO_TOT)  v = w_msk[((co - 2 * KK) * IC + ci) * KK + tap];
            sw[tap * 16 + lc] = v;
        }
        __syncthreads();

        #pragma unroll (K)
        for (int tap = 0; tap < KK; tap++) {
            const int dy = tap / K, dx = tap - dy * K;
            const float xv0 = sx[(ty + dy) * P + tx + dx];
            const float xv1 = sx[(ty + 8 + dy) * P + tx + dx];
            const u64 xp0 = pack2(xv0, xv0);
            const u64 xp1 = pack2(xv1, xv1);
            const u64* w2 = reinterpret_cast<const u64*>(&sw[tap * 16]);
            #pragma unroll
            for (int i = 0; i < 8; i++) {
                u64 w = w2[i];                // broadcast LDS.64
                ffma2(acc0[i], xp0, w);
                ffma2(acc1[i], xp1, w);
            }
        }
        __syncthreads();
    }

    const int oy = by0 + ty, ox = bx0 + tx;
    const int idx0 = oy * IW + ox;
    const int idx1 = (oy + 8) * IW + ox;
    #pragma unroll
    for (int i = 0; i < 8; i++) {
        float2 v0 = unpack2(acc0[i]);
        float2 v1 = unpack2(acc1[i]);
        #pragma unroll
        for (int h = 0; h < 2; h++) {
            const int co = co0 + 2 * i + h;
            const float a0 = h ? v0.y : v0.x;
            const float a1 = h ? v1.y : v1.x;
            if (co < 2 * KK) {
                float bo = b_off[co];
                offp[(b * 2 * KK + co) * IHW + idx0] = a0 + bo;
                offp[(b * 2 * KK + co) * IHW + idx1] = a1 + bo;
            } else if (co < CO_TOT) {
                int cm = co - 2 * KK;
                float bm = b_msk[cm];
                mskp[(b * KK + cm) * IHW + idx0] = 1.f / (1.f + expf(-(a0 + bm)));
                mskp[(b * KK + cm) * IHW + idx1] = 1.f / (1.f + expf(-(a1 + bm)));
            }
        }
    }
}

// ---------------------------------------------------------------------------
// Weight transpose for all branches: w_dcn[o][c][kk] -> g_wt[kk][o*64+c]
// ---------------------------------------------------------------------------
__global__ void wt_transpose_all(const float* __restrict__ w3,
                                 const float* __restrict__ w5,
                                 const float* __restrict__ w7)
{
    int i = blockIdx.x * 256 + threadIdx.x;
    if (i < 9 * 4096) {
        g_wt3[i] = w3[(i & 4095) * 9 + (i >> 12)];
    } else if (i < (9 + 25) * 4096) {
        int j = i - 9 * 4096;
        g_wt5[j] = w5[(j & 4095) * 25 + (j >> 12)];
    } else if (i < (9 + 25 + 49) * 4096) {
        int j = i - (9 + 25) * 4096;
        g_wt7[j] = w7[(j & 4095) * 49 + (j >> 12)];
    }
}

// ---------------------------------------------------------------------------
// Fused deformable sample + per-tap 64x64 matvec.
// 32 pixels/block, 128 threads. Matvec: each thread 4 o-channels x 4 pixels,
// f32x2 over pixel pairs. grid: NB*IHW/32 = 400 blocks.
// ---------------------------------------------------------------------------
template<int K>
__global__ void __launch_bounds__(128) dcn_sample(
    const float* __restrict__ x, float* __restrict__ out, int ch_base)
{
    constexpr int KK  = K * K;
    constexpr int PAD = K / 2;
    constexpr int WP  = 68;   // s_w pitch  ([o][c])
    constexpr int SP  = 36;   // s_samp pitch ([c][p]): 32 px + 4 pad

    const float* offp = (K == 3) ? g_off3 : (K == 5) ? g_off5 : g_off7;
    const float* mskp = (K == 3) ? g_msk3 : (K == 5) ? g_msk5 : g_msk7;
    const float* wtp  = (K == 3) ? g_wt3  : (K == 5) ? g_wt5  : g_wt7;

    __shared__ __align__(16) float s_w[64 * WP];
    __shared__ __align__(16) float s_samp[64 * SP];
    __shared__ float s_py[32], s_px[32], s_m[32];

    const int tid  = threadIdx.x;
    const int pix0 = blockIdx.x * 32;
    const int b    = pix0 / IHW;
    const int rem0 = pix0 - b * IHW;

    const int o0 = tid & 15;         // matvec: o0, o0+16, o0+32, o0+48
    const int pb = (tid >> 4) * 4;   // matvec pixel base (0..28)
    const int sp = tid & 31;         // sampling: pixel
    const int sc = tid >> 5;         // sampling: channel group 0..3 (16 ch each)

    u64 acc[4][2];
    #pragma unroll
    for (int q = 0; q < 4; q++) { acc[q][0] = 0ull; acc[q][1] = 0ull; }

    for (int kk = 0; kk < KK; kk++) {
        if (tid < 32) {
            int rem = rem0 + tid;
            int h = rem / IW, w = rem - h * IW;
            float oy = offp[(b * 2 * KK + 2 * kk    ) * IHW + rem];
            float ox = offp[(b * 2 * KK + 2 * kk + 1) * IHW + rem];
            s_py[tid] = (float)(h - PAD + kk / K) + oy;
            s_px[tid] = (float)(w - PAD + kk % K) + ox;
            s_m[tid]  = mskp[(b * KK + kk) * IHW + rem];
        }
        for (int i = tid; i < 4096; i += 128)
            s_w[(i >> 6) * WP + (i & 63)] = wtp[kk * 4096 + i];
        __syncthreads();

        // bilinear gather: pixel sp, 16 channels (sc*16 .. +15)
        {
            const float py = s_py[sp], px = s_px[sp], m = s_m[sp];
            const float y0f = floorf(py), x0f = floorf(px);
            const int   y0  = (int)y0f,   x0  = (int)x0f;
            const float wy1 = py - y0f, wx1 = px - x0f;
            const float wy0 = 1.f - wy1, wx0 = 1.f - wx1;
            const bool vy0 = (y0 >= 0) && (y0 < IH);
            const bool vy1 = (y0 + 1 >= 0) && (y0 + 1 < IH);
            const bool vx0 = (x0 >= 0) && (x0 < IW);
            const bool vx1 = (x0 + 1 >= 0) && (x0 + 1 < IW);
            const int y0c = min(max(y0, 0), IH - 1);
            const int y1c = min(max(y0 + 1, 0), IH - 1);
            const int x0c = min(max(x0, 0), IW - 1);
            const int x1c = min(max(x0 + 1, 0), IW - 1);
            const float w00 = wy0 * wx0 * ((vy0 && vx0) ? 1.f : 0.f) * m;
            const float w01 = wy0 * wx1 * ((vy0 && vx1) ? 1.f : 0.f) * m;
            const float w10 = wy1 * wx0 * ((vy1 && vx0) ? 1.f : 0.f) * m;
            const float w11 = wy1 * wx1 * ((vy1 && vx1) ? 1.f : 0.f) * m;
            const int i00 = y0c * IW + x0c, i01 = y0c * IW + x1c;
            const int i10 = y1c * IW + x0c, i11 = y1c * IW + x1c;
            const float* base = x + b * IC * IHW + sc * 16 * IHW;
            #pragma unroll
            for (int j = 0; j < 16; j++) {
                const float* xp = base + j * IHW;
                float v = w00 * xp[i00] + w01 * xp[i01]
                        + w10 * xp[i10] + w11 * xp[i11];
                s_samp[(sc * 16 + j) * SP + sp] = v;
            }
        }
        __syncthreads();

        // matvec: 4 o x 4 px, f32x2 over pixel pairs
        #pragma unroll 4
        for (int c = 0; c < 64; c += 4) {
            const float4 wA = *(const float4*)&s_w[(o0     ) * WP + c];
            const float4 wB = *(const float4*)&s_w[(o0 + 16) * WP + c];
            const float4 wC = *(const float4*)&s_w[(o0 + 32) * WP + c];
            const float4 wD = *(const float4*)&s_w[(o0 + 48) * WP + c];
            const float4 sA = *(const float4*)&s_samp[(c + 0) * SP + pb];
            const float4 sB = *(const float4*)&s_samp[(c + 1) * SP + pb];
            const float4 sC = *(const float4*)&s_samp[(c + 2) * SP + pb];
            const float4 sD = *(const float4*)&s_samp[(c + 3) * SP + pb];
            const u64 sAl = pack2(sA.x, sA.y), sAh = pack2(sA.z, sA.w);
            const u64 sBl = pack2(sB.x, sB.y), sBh = pack2(sB.z, sB.w);
            const u64 sCl = pack2(sC.x, sC.y), sCh = pack2(sC.z, sC.w);
            const u64 sDl = pack2(sD.x, sD.y), sDh = pack2(sD.z, sD.w);
            #pragma unroll
            for (int q = 0; q < 4; q++) {
                const float4 w = (q == 0) ? wA : (q == 1) ? wB : (q == 2) ? wC : wD;
                u64 w0 = pack2(w.x, w.x);
                u64 w1 = pack2(w.y, w.y);
                u64 w2 = pack2(w.z, w.z);
                u64 w3 = pack2(w.w, w.w);
                ffma2(acc[q][0], w0, sAl); ffma2(acc[q][1], w0, sAh);
                ffma2(acc[q][0], w1, sBl); ffma2(acc[q][1], w1, sBh);
                ffma2(acc[q][0], w2, sCl); ffma2(acc[q][1], w2, sCh);
                ffma2(acc[q][0], w3, sDl); ffma2(acc[q][1], w3, sDh);
            }
        }
        __syncthreads();
    }

    // stage to smem for coalesced output stores
    #pragma unroll
    for (int q = 0; q < 4; q++) {
        float2 lo = unpack2(acc[q][0]);
        float2 hi = unpack2(acc[q][1]);
        const int oo = o0 + q * 16;
        s_samp[oo * SP + pb + 0] = lo.x;
        s_samp[oo * SP + pb + 1] = lo.y;
        s_samp[oo * SP + pb + 2] = hi.x;
        s_samp[oo * SP + pb + 3] = hi.y;
    }
    __syncthreads();
    for (int i = tid; i < 2048; i += 128) {
        const int oo = i >> 5, p = i & 31;
        out[(b * 192 + ch_base + oo) * IHW + rem0 + p] = s_samp[oo * SP + p];
    }
}

// ---------------------------------------------------------------------------
extern "C" void kernel_launch(void* const* d_in, const int* in_sizes, int n_in,
                              void* d_out, int out_size)
{
    const float* x = (const float*)d_in[0];
    float* out = (float*)d_out;

    wt_transpose_all<<<(83 * 4096 + 255) / 256, 256>>>(
        (const float*)d_in[5], (const float*)d_in[10], (const float*)d_in[15]);

    conv_offmask<3, 2><<<dim3(5, 5 * 2, NB), 128>>>(x,
        (const float*)d_in[1], (const float*)d_in[2],
        (const float*)d_in[3], (const float*)d_in[4]);
    dcn_sample<3><<<NB * IHW / 32, 128>>>(x, out, 0);

    conv_offmask<5, 5><<<dim3(5, 5 * 5, NB), 128>>>(x,
        (const float*)d_in[6], (const float*)d_in[7],
        (const float*)d_in[8], (const float*)d_in[9]);
    dcn_sample<5><<<NB * IHW / 32, 128>>>(x, out, 64);

    conv_offmask<7, 10><<<dim3(5, 5 * 10, NB), 128>>>(x,
        (const float*)d_in[11], (const float*)d_in[12],
        (const float*)d_in[13], (const float*)d_in[14]);
    dcn_sample<7><<<NB * IHW / 32, 128>>>(x, out, 128);
}

// round 6
// speedup vs baseline: 1.6471x; 1.4944x over previous
#include <cuda_runtime.h>
#include <math.h>

constexpr int NB  = 2;
constexpr int IC  = 64;
constexpr int IH  = 80;
constexpr int IW  = 80;
constexpr int IHW = IH * IW;   // 6400
constexpr int NSPLIT  = 4;
constexpr int CICHUNK = IC / NSPLIT;   // 16

// Concatenated offset/mask layouts (branch bases)
constexpr int OFF_B3 = 0;
constexpr int OFF_B5 = NB * 18 * IHW;               // 230400
constexpr int OFF_B7 = OFF_B5 + NB * 50 * IHW;      // 870400
constexpr int OFF_TOT = OFF_B7 + NB * 98 * IHW;     // 2124800
constexpr int MSK_B3 = 0;
constexpr int MSK_B5 = NB * 9 * IHW;                // 115200
constexpr int MSK_B7 = MSK_B5 + NB * 25 * IHW;      // 435200
constexpr int MSK_TOT = MSK_B7 + NB * 49 * IHW;     // 1062400
constexpr int WT_B3 = 0;
constexpr int WT_B5 = 9 * 4096;
constexpr int WT_B7 = (9 + 25) * 4096;

__device__ float g_offP[NSPLIT * OFF_TOT];   // partial conv sums (no bias)
__device__ float g_mskP[NSPLIT * MSK_TOT];
__device__ float g_offF[OFF_TOT];            // final offsets (bias applied)
__device__ float g_mskF[MSK_TOT];            // final masks (sigmoid applied)
__device__ float g_wt[(9 + 25 + 49) * 4096]; // transposed dcn weights: [kk][o*64+c]

// ---- f32x2 packed helpers (sm_103a) ----
using u64 = unsigned long long;
__device__ __forceinline__ u64 pack2(float a, float b) {
    u64 r; asm("mov.b64 %0, {%1, %2};" : "=l"(r) : "f"(a), "f"(b)); return r;
}
__device__ __forceinline__ void ffma2(u64& d, u64 a, u64 b) {
    asm("fma.rn.f32x2 %0, %1, %2, %3;" : "=l"(d) : "l"(a), "l"(b), "l"(d));
}
__device__ __forceinline__ float2 unpack2(u64 v) {
    float x, y; asm("mov.b64 {%0, %1}, %2;" : "=f"(x), "=f"(y) : "l"(v));
    return make_float2(x, y);
}

// ---------------------------------------------------------------------------
// Conv body: 16x16 spatial tile, 128 threads, 2 px x 16 co per thread,
// ci-chunk of 16 channels (split-K), partial sums to g_offP/g_mskP.
// ---------------------------------------------------------------------------
template<int K, int NG>
__device__ __forceinline__ void conv_body(
    int lb, const float* __restrict__ x,
    const float* __restrict__ w_off, const float* __restrict__ w_msk,
    int offbase, int mskbase, float* sx, float* sw)
{
    constexpr int KK  = K * K;
    constexpr int PAD = K / 2;
    constexpr int CO_TOT = 3 * KK;
    constexpr int TS  = 16 + K - 1;
    constexpr int P   = TS | 1;

    const int s    = lb & 3;
    int r          = lb >> 2;
    const int tile = r % 25;  r /= 25;
    const int grp  = r % NG;
    const int b    = r / NG;

    const int tid = threadIdx.x;
    const int tx  = tid & 15;
    const int ty  = tid >> 4;
    const int bx0 = (tile % 5) * 16;
    const int by0 = (tile / 5) * 16;
    const int co0 = grp * 16;
    const int ci0 = s * CICHUNK;

    u64 acc0[8], acc1[8];
    #pragma unroll
    for (int i = 0; i < 8; i++) { acc0[i] = 0ull; acc1[i] = 0ull; }

    for (int ci = ci0; ci < ci0 + CICHUNK; ci++) {
        const float* xp = x + (b * IC + ci) * IHW;
        for (int i = tid; i < TS * TS; i += 128) {
            int ry = i / TS, rx = i - ry * TS;
            int gy = by0 - PAD + ry, gx = bx0 - PAD + rx;
            float v = 0.f;
            if (gy >= 0 && gy < IH && gx >= 0 && gx < IW) v = xp[gy * IW + gx];
            sx[ry * P + rx] = v;
        }
        for (int i = tid; i < 16 * KK; i += 128) {
            int lc = i / KK, tap = i - lc * KK;
            int co = co0 + lc;
            float v = 0.f;
            if (co < 2 * KK)       v = w_off[(co * IC + ci) * KK + tap];
            else if (co < CO_TOT)  v = w_msk[((co - 2 * KK) * IC + ci) * KK + tap];
            sw[tap * 16 + lc] = v;
        }
        __syncthreads();

        #pragma unroll
        for (int tap = 0; tap < KK; tap++) {
            const int dy = tap / K, dx = tap - dy * K;
            const float xv0 = sx[(ty + dy) * P + tx + dx];
            const float xv1 = sx[(ty + 8 + dy) * P + tx + dx];
            const u64 xp0 = pack2(xv0, xv0);
            const u64 xp1 = pack2(xv1, xv1);
            const u64* w2 = reinterpret_cast<const u64*>(&sw[tap * 16]);
            #pragma unroll
            for (int i = 0; i < 8; i++) {
                u64 w = w2[i];
                ffma2(acc0[i], xp0, w);
                ffma2(acc1[i], xp1, w);
            }
        }
        __syncthreads();
    }

    float* op = g_offP + (size_t)s * OFF_TOT + offbase;
    float* mp = g_mskP + (size_t)s * MSK_TOT + mskbase;
    const int oy = by0 + ty, ox = bx0 + tx;
    const int idx0 = oy * IW + ox;
    const int idx1 = (oy + 8) * IW + ox;
    #pragma unroll
    for (int i = 0; i < 8; i++) {
        float2 v0 = unpack2(acc0[i]);
        float2 v1 = unpack2(acc1[i]);
        #pragma unroll
        for (int h = 0; h < 2; h++) {
            const int co = co0 + 2 * i + h;
            const float a0 = h ? v0.y : v0.x;
            const float a1 = h ? v1.y : v1.x;
            if (co < 2 * KK) {
                op[(b * 2 * KK + co) * IHW + idx0] = a0;
                op[(b * 2 * KK + co) * IHW + idx1] = a1;
            } else if (co < CO_TOT) {
                const int cm = co - 2 * KK;
                mp[(b * KK + cm) * IHW + idx0] = a0;
                mp[(b * KK + cm) * IHW + idx1] = a1;
            }
        }
    }
}

// Merged conv: blocks [0,400)=k3, [400,1400)=k5, [1400,3400)=k7
__global__ void __launch_bounds__(128) conv_all(
    const float* __restrict__ x,
    const float* __restrict__ w3o, const float* __restrict__ w3m,
    const float* __restrict__ w5o, const float* __restrict__ w5m,
    const float* __restrict__ w7o, const float* __restrict__ w7m)
{
    __shared__ __align__(16) float sx[22 * 23];   // max (K=7)
    __shared__ __align__(16) float sw[49 * 16];

    const int bid = blockIdx.x;
    if (bid < 400)        conv_body<3, 2>(bid,        x, w3o, w3m, OFF_B3, MSK_B3, sx, sw);
    else if (bid < 1400)  conv_body<5, 5>(bid - 400,  x, w5o, w5m, OFF_B5, MSK_B5, sx, sw);
    else                  conv_body<7,10>(bid - 1400, x, w7o, w7m, OFF_B7, MSK_B7, sx, sw);
}

// ---------------------------------------------------------------------------
// Reduce partials: offsets += bias; masks = sigmoid(sum + bias)
// ---------------------------------------------------------------------------
__global__ void reduce_offmask(
    const float* __restrict__ b3o, const float* __restrict__ b3m,
    const float* __restrict__ b5o, const float* __restrict__ b5m,
    const float* __restrict__ b7o, const float* __restrict__ b7m)
{
    int i = blockIdx.x * 256 + threadIdx.x;
    if (i < OFF_TOT) {
        float v = g_offP[i] + g_offP[OFF_TOT + i]
                + g_offP[2 * OFF_TOT + i] + g_offP[3 * (size_t)OFF_TOT + i];
        const float* bp; int local, kk2;
        if (i < OFF_B5)      { bp = b3o; local = i;          kk2 = 18; }
        else if (i < OFF_B7) { bp = b5o; local = i - OFF_B5; kk2 = 50; }
        else                 { bp = b7o; local = i - OFF_B7; kk2 = 98; }
        int co = (local / IHW) % kk2;
        g_offF[i] = v + bp[co];
    } else {
        int j = i - OFF_TOT;
        if (j < MSK_TOT) {
            float v = g_mskP[j] + g_mskP[MSK_TOT + j]
                    + g_mskP[2 * MSK_TOT + j] + g_mskP[3 * (size_t)MSK_TOT + j];
            const float* bp; int local, kk;
            if (j < MSK_B5)      { bp = b3m; local = j;          kk = 9;  }
            else if (j < MSK_B7) { bp = b5m; local = j - MSK_B5; kk = 25; }
            else                 { bp = b7m; local = j - MSK_B7; kk = 49; }
            int cm = (local / IHW) % kk;
            g_mskF[j] = 1.f / (1.f + expf(-(v + bp[cm])));
        }
    }
}

// ---------------------------------------------------------------------------
// Weight transpose: w_dcn[o][c][kk] -> g_wt[base + kk*4096 + o*64 + c]
// (m = o*64+c is the flattened [o][c] index; sampler loads s_w[o][c] from this)
// ---------------------------------------------------------------------------
__global__ void wt_transpose_all(const float* __restrict__ w3,
                                 const float* __restrict__ w5,
                                 const float* __restrict__ w7)
{
    int i = blockIdx.x * 256 + threadIdx.x;
    if (i < 9 * 4096) {
        g_wt[WT_B3 + i] = w3[(i & 4095) * 9 + (i >> 12)];
    } else if (i < (9 + 25) * 4096) {
        int j = i - 9 * 4096;
        g_wt[WT_B5 + j] = w5[(j & 4095) * 25 + (j >> 12)];
    } else if (i < (9 + 25 + 49) * 4096) {
        int j = i - (9 + 25) * 4096;
        g_wt[WT_B7 + j] = w7[(j & 4095) * 49 + (j >> 12)];
    }
}

// ---------------------------------------------------------------------------
// Sample body: 32 pixels/block, 128 threads, per-tap bilinear gather + 64x64
// matvec (4 o x 4 px per thread, f32x2 over pixel pairs).
// ---------------------------------------------------------------------------
template<int K>
__device__ __forceinline__ void sample_body(
    int lb, const float* __restrict__ x, float* __restrict__ out,
    int ch_base, int offbase, int mskbase, int wtbase,
    float* s_w, float* s_samp, float* s_py, float* s_px, float* s_m)
{
    constexpr int KK  = K * K;
    constexpr int PAD = K / 2;
    constexpr int WP  = 68;
    constexpr int SP  = 36;

    const float* offp = g_offF + offbase;
    const float* mskp = g_mskF + mskbase;
    const float* wtp  = g_wt  + wtbase;

    const int tid  = threadIdx.x;
    const int pix0 = lb * 32;
    const int b    = pix0 / IHW;
    const int rem0 = pix0 - b * IHW;

    const int o0 = tid & 15;
    const int pb = (tid >> 4) * 4;
    const int sp = tid & 31;
    const int sc = tid >> 5;

    u64 acc[4][2];
    #pragma unroll
    for (int q = 0; q < 4; q++) { acc[q][0] = 0ull; acc[q][1] = 0ull; }

    for (int kk = 0; kk < KK; kk++) {
        if (tid < 32) {
            int rem = rem0 + tid;
            int h = rem / IW, w = rem - h * IW;
            float oy = offp[(b * 2 * KK + 2 * kk    ) * IHW + rem];
            float ox = offp[(b * 2 * KK + 2 * kk + 1) * IHW + rem];
            s_py[tid] = (float)(h - PAD + kk / K) + oy;
            s_px[tid] = (float)(w - PAD + kk % K) + ox;
            s_m[tid]  = mskp[(b * KK + kk) * IHW + rem];
        }
        for (int i = tid; i < 4096; i += 128)
            s_w[(i >> 6) * WP + (i & 63)] = wtp[kk * 4096 + i];
        __syncthreads();

        {
            const float py = s_py[sp], px = s_px[sp], m = s_m[sp];
            const float y0f = floorf(py), x0f = floorf(px);
            const int   y0  = (int)y0f,   x0  = (int)x0f;
            const float wy1 = py - y0f, wx1 = px - x0f;
            const float wy0 = 1.f - wy1, wx0 = 1.f - wx1;
            const bool vy0 = (y0 >= 0) && (y0 < IH);
            const bool vy1 = (y0 + 1 >= 0) && (y0 + 1 < IH);
            const bool vx0 = (x0 >= 0) && (x0 < IW);
            const bool vx1 = (x0 + 1 >= 0) && (x0 + 1 < IW);
            const int y0c = min(max(y0, 0), IH - 1);
            const int y1c = min(max(y0 + 1, 0), IH - 1);
            const int x0c = min(max(x0, 0), IW - 1);
            const int x1c = min(max(x0 + 1, 0), IW - 1);
            const float w00 = wy0 * wx0 * ((vy0 && vx0) ? 1.f : 0.f) * m;
            const float w01 = wy0 * wx1 * ((vy0 && vx1) ? 1.f : 0.f) * m;
            const float w10 = wy1 * wx0 * ((vy1 && vx0) ? 1.f : 0.f) * m;
            const float w11 = wy1 * wx1 * ((vy1 && vx1) ? 1.f : 0.f) * m;
            const int i00 = y0c * IW + x0c, i01 = y0c * IW + x1c;
            const int i10 = y1c * IW + x0c, i11 = y1c * IW + x1c;
            const float* base = x + b * IC * IHW + sc * 16 * IHW;
            #pragma unroll
            for (int j = 0; j < 16; j++) {
                const float* xp = base + j * IHW;
                float v = w00 * xp[i00] + w01 * xp[i01]
                        + w10 * xp[i10] + w11 * xp[i11];
                s_samp[(sc * 16 + j) * SP + sp] = v;
            }
        }
        __syncthreads();

        #pragma unroll 4
        for (int c = 0; c < 64; c += 4) {
            const float4 wA = *(const float4*)&s_w[(o0     ) * WP + c];
            const float4 wB = *(const float4*)&s_w[(o0 + 16) * WP + c];
            const float4 wC = *(const float4*)&s_w[(o0 + 32) * WP + c];
            const float4 wD = *(const float4*)&s_w[(o0 + 48) * WP + c];
            const float4 sA = *(const float4*)&s_samp[(c + 0) * SP + pb];
            const float4 sB = *(const float4*)&s_samp[(c + 1) * SP + pb];
            const float4 sC = *(const float4*)&s_samp[(c + 2) * SP + pb];
            const float4 sD = *(const float4*)&s_samp[(c + 3) * SP + pb];
            const u64 sAl = pack2(sA.x, sA.y), sAh = pack2(sA.z, sA.w);
            const u64 sBl = pack2(sB.x, sB.y), sBh = pack2(sB.z, sB.w);
            const u64 sCl = pack2(sC.x, sC.y), sCh = pack2(sC.z, sC.w);
            const u64 sDl = pack2(sD.x, sD.y), sDh = pack2(sD.z, sD.w);
            #pragma unroll
            for (int q = 0; q < 4; q++) {
                const float4 w = (q == 0) ? wA : (q == 1) ? wB : (q == 2) ? wC : wD;
                u64 w0 = pack2(w.x, w.x);
                u64 w1 = pack2(w.y, w.y);
                u64 w2 = pack2(w.z, w.z);
                u64 w3 = pack2(w.w, w.w);
                ffma2(acc[q][0], w0, sAl); ffma2(acc[q][1], w0, sAh);
                ffma2(acc[q][0], w1, sBl); ffma2(acc[q][1], w1, sBh);
                ffma2(acc[q][0], w2, sCl); ffma2(acc[q][1], w2, sCh);
                ffma2(acc[q][0], w3, sDl); ffma2(acc[q][1], w3, sDh);
            }
        }
        __syncthreads();
    }

    #pragma unroll
    for (int q = 0; q < 4; q++) {
        float2 lo = unpack2(acc[q][0]);
        float2 hi = unpack2(acc[q][1]);
        const int oo = o0 + q * 16;
        s_samp[oo * SP + pb + 0] = lo.x;
        s_samp[oo * SP + pb + 1] = lo.y;
        s_samp[oo * SP + pb + 2] = hi.x;
        s_samp[oo * SP + pb + 3] = hi.y;
    }
    __syncthreads();
    for (int i = tid; i < 2048; i += 128) {
        const int oo = i >> 5, p = i & 31;
        out[(b * 192 + ch_base + oo) * IHW + rem0 + p] = s_samp[oo * SP + p];
    }
}

// Merged sampler: blocks [0,400)=k3, [400,800)=k5, [800,1200)=k7
__global__ void __launch_bounds__(128) sample_all(
    const float* __restrict__ x, float* __restrict__ out)
{
    __shared__ __align__(16) float s_w[64 * 68];
    __shared__ __align__(16) float s_samp[64 * 36];
    __shared__ float s_py[32], s_px[32], s_m[32];

    const int bid = blockIdx.x;
    if (bid < 400)
        sample_body<3>(bid,       x, out, 0,   OFF_B3, MSK_B3, WT_B3, s_w, s_samp, s_py, s_px, s_m);
    else if (bid < 800)
        sample_body<5>(bid - 400, x, out, 64,  OFF_B5, MSK_B5, WT_B5, s_w, s_samp, s_py, s_px, s_m);
    else
        sample_body<7>(bid - 800, x, out, 128, OFF_B7, MSK_B7, WT_B7, s_w, s_samp, s_py, s_px, s_m);
}

// ---------------------------------------------------------------------------
extern "C" void kernel_launch(void* const* d_in, const int* in_sizes, int n_in,
                              void* d_out, int out_size)
{
    const float* x = (const float*)d_in[0];
    float* out = (float*)d_out;

    conv_all<<<3400, 128>>>(x,
        (const float*)d_in[1],  (const float*)d_in[3],
        (const float*)d_in[6],  (const float*)d_in[8],
        (const float*)d_in[11], (const float*)d_in[13]);

    wt_transpose_all<<<(83 * 4096 + 255) / 256, 256>>>(
        (const float*)d_in[5], (const float*)d_in[10], (const float*)d_in[15]);

    reduce_offmask<<<(OFF_TOT + MSK_TOT + 255) / 256, 256>>>(
        (const float*)d_in[2],  (const float*)d_in[4],
        (const float*)d_in[7],  (const float*)d_in[9],
        (const float*)d_in[12], (const float*)d_in[14]);

    sample_all<<<1200, 128>>>(x, out);
}

// round 7
// speedup vs baseline: 1.8301x; 1.1111x over previous
#include <cuda_runtime.h>
#include <math.h>

constexpr int NB  = 2;
constexpr int IC  = 64;
constexpr int IH  = 80;
constexpr int IW  = 80;
constexpr int IHW = IH * IW;   // 6400
constexpr int NSPLIT  = 4;
constexpr int CICHUNK = IC / NSPLIT;   // 16

// Concatenated offset/mask layouts (branch bases)
constexpr int OFF_B3 = 0;
constexpr int OFF_B5 = NB * 18 * IHW;
constexpr int OFF_B7 = OFF_B5 + NB * 50 * IHW;
constexpr int OFF_TOT = OFF_B7 + NB * 98 * IHW;
constexpr int MSK_B3 = 0;
constexpr int MSK_B5 = NB * 9 * IHW;
constexpr int MSK_B7 = MSK_B5 + NB * 25 * IHW;
constexpr int MSK_TOT = MSK_B7 + NB * 49 * IHW;
constexpr int WT_B3 = 0;
constexpr int WT_B5 = 9 * 4096;
constexpr int WT_B7 = (9 + 25) * 4096;
constexpr int PCH   = NB * 64 * IHW;   // one partial-chunk slab: 819200

__device__ float g_offP[NSPLIT * OFF_TOT];
__device__ float g_mskP[NSPLIT * MSK_TOT];
__device__ float g_offF[OFF_TOT];
__device__ float g_mskF[MSK_TOT];
__device__ float g_wt[(9 + 25 + 49) * 4096];  // [kk][o*64+c]
__device__ float g_outP5[2 * PCH];            // k5 tap-chunk partials
__device__ float g_outP7[4 * PCH];            // k7 tap-chunk partials

// ---- f32x2 packed helpers (sm_103a) ----
using u64 = unsigned long long;
__device__ __forceinline__ u64 pack2(float a, float b) {
    u64 r; asm("mov.b64 %0, {%1, %2};" : "=l"(r) : "f"(a), "f"(b)); return r;
}
__device__ __forceinline__ void ffma2(u64& d, u64 a, u64 b) {
    asm("fma.rn.f32x2 %0, %1, %2, %3;" : "=l"(d) : "l"(a), "l"(b), "l"(d));
}
__device__ __forceinline__ float2 unpack2(u64 v) {
    float x, y; asm("mov.b64 {%0, %1}, %2;" : "=f"(x), "=f"(y) : "l"(v));
    return make_float2(x, y);
}

// ---------------------------------------------------------------------------
// Conv body: 16x16 spatial tile, 128 threads, 2 px x 16 co, split-K over ci.
// ---------------------------------------------------------------------------
template<int K, int NG>
__device__ __forceinline__ void conv_body(
    int lb, const float* __restrict__ x,
    const float* __restrict__ w_off, const float* __restrict__ w_msk,
    int offbase, int mskbase, float* sx, float* sw)
{
    constexpr int KK  = K * K;
    constexpr int PAD = K / 2;
    constexpr int CO_TOT = 3 * KK;
    constexpr int TS  = 16 + K - 1;
    constexpr int P   = TS | 1;

    const int s    = lb & 3;
    int r          = lb >> 2;
    const int tile = r % 25;  r /= 25;
    const int grp  = r % NG;
    const int b    = r / NG;

    const int tid = threadIdx.x;
    const int tx  = tid & 15;
    const int ty  = tid >> 4;
    const int bx0 = (tile % 5) * 16;
    const int by0 = (tile / 5) * 16;
    const int co0 = grp * 16;
    const int ci0 = s * CICHUNK;

    u64 acc0[8], acc1[8];
    #pragma unroll
    for (int i = 0; i < 8; i++) { acc0[i] = 0ull; acc1[i] = 0ull; }

    for (int ci = ci0; ci < ci0 + CICHUNK; ci++) {
        const float* xp = x + (b * IC + ci) * IHW;
        for (int i = tid; i < TS * TS; i += 128) {
            int ry = i / TS, rx = i - ry * TS;
            int gy = by0 - PAD + ry, gx = bx0 - PAD + rx;
            float v = 0.f;
            if (gy >= 0 && gy < IH && gx >= 0 && gx < IW) v = xp[gy * IW + gx];
            sx[ry * P + rx] = v;
        }
        for (int i = tid; i < 16 * KK; i += 128) {
            int lc = i / KK, tap = i - lc * KK;
            int co = co0 + lc;
            float v = 0.f;
            if (co < 2 * KK)       v = w_off[(co * IC + ci) * KK + tap];
            else if (co < CO_TOT)  v = w_msk[((co - 2 * KK) * IC + ci) * KK + tap];
            sw[tap * 16 + lc] = v;
        }
        __syncthreads();

        #pragma unroll
        for (int tap = 0; tap < KK; tap++) {
            const int dy = tap / K, dx = tap - dy * K;
            const float xv0 = sx[(ty + dy) * P + tx + dx];
            const float xv1 = sx[(ty + 8 + dy) * P + tx + dx];
            const u64 xp0 = pack2(xv0, xv0);
            const u64 xp1 = pack2(xv1, xv1);
            const u64* w2 = reinterpret_cast<const u64*>(&sw[tap * 16]);
            #pragma unroll
            for (int i = 0; i < 8; i++) {
                u64 w = w2[i];
                ffma2(acc0[i], xp0, w);
                ffma2(acc1[i], xp1, w);
            }
        }
        __syncthreads();
    }

    float* op = g_offP + (size_t)s * OFF_TOT + offbase;
    float* mp = g_mskP + (size_t)s * MSK_TOT + mskbase;
    const int oy = by0 + ty, ox = bx0 + tx;
    const int idx0 = oy * IW + ox;
    const int idx1 = (oy + 8) * IW + ox;
    #pragma unroll
    for (int i = 0; i < 8; i++) {
        float2 v0 = unpack2(acc0[i]);
        float2 v1 = unpack2(acc1[i]);
        #pragma unroll
        for (int h = 0; h < 2; h++) {
            const int co = co0 + 2 * i + h;
            const float a0 = h ? v0.y : v0.x;
            const float a1 = h ? v1.y : v1.x;
            if (co < 2 * KK) {
                op[(b * 2 * KK + co) * IHW + idx0] = a0;
                op[(b * 2 * KK + co) * IHW + idx1] = a1;
            } else if (co < CO_TOT) {
                const int cm = co - 2 * KK;
                mp[(b * KK + cm) * IHW + idx0] = a0;
                mp[(b * KK + cm) * IHW + idx1] = a1;
            }
        }
    }
}

// Merged conv: blocks [0,400)=k3, [400,1400)=k5, [1400,3400)=k7
__global__ void __launch_bounds__(128) conv_all(
    const float* __restrict__ x,
    const float* __restrict__ w3o, const float* __restrict__ w3m,
    const float* __restrict__ w5o, const float* __restrict__ w5m,
    const float* __restrict__ w7o, const float* __restrict__ w7m)
{
    __shared__ __align__(16) float sx[22 * 23];
    __shared__ __align__(16) float sw[49 * 16];

    const int bid = blockIdx.x;
    if (bid < 400)        conv_body<3, 2>(bid,        x, w3o, w3m, OFF_B3, MSK_B3, sx, sw);
    else if (bid < 1400)  conv_body<5, 5>(bid - 400,  x, w5o, w5m, OFF_B5, MSK_B5, sx, sw);
    else                  conv_body<7,10>(bid - 1400, x, w7o, w7m, OFF_B7, MSK_B7, sx, sw);
}

// ---------------------------------------------------------------------------
// Reduce conv partials: offsets += bias; masks = sigmoid(sum + bias)
// ---------------------------------------------------------------------------
__global__ void reduce_offmask(
    const float* __restrict__ b3o, const float* __restrict__ b3m,
    const float* __restrict__ b5o, const float* __restrict__ b5m,
    const float* __restrict__ b7o, const float* __restrict__ b7m)
{
    int i = blockIdx.x * 256 + threadIdx.x;
    if (i < OFF_TOT) {
        float v = g_offP[i] + g_offP[OFF_TOT + i]
                + g_offP[2 * OFF_TOT + i] + g_offP[3 * (size_t)OFF_TOT + i];
        const float* bp; int local, kk2;
        if (i < OFF_B5)      { bp = b3o; local = i;          kk2 = 18; }
        else if (i < OFF_B7) { bp = b5o; local = i - OFF_B5; kk2 = 50; }
        else                 { bp = b7o; local = i - OFF_B7; kk2 = 98; }
        int co = (local / IHW) % kk2;
        g_offF[i] = v + bp[co];
    } else {
        int j = i - OFF_TOT;
        if (j < MSK_TOT) {
            float v = g_mskP[j] + g_mskP[MSK_TOT + j]
                    + g_mskP[2 * MSK_TOT + j] + g_mskP[3 * (size_t)MSK_TOT + j];
            const float* bp; int local, kk;
            if (j < MSK_B5)      { bp = b3m; local = j;          kk = 9;  }
            else if (j < MSK_B7) { bp = b5m; local = j - MSK_B5; kk = 25; }
            else                 { bp = b7m; local = j - MSK_B7; kk = 49; }
            int cm = (local / IHW) % kk;
            g_mskF[j] = 1.f / (1.f + expf(-(v + bp[cm])));
        }
    }
}

// ---------------------------------------------------------------------------
// Weight transpose: w_dcn[o][c][kk] -> g_wt[base + kk*4096 + o*64 + c]
// ---------------------------------------------------------------------------
__global__ void wt_transpose_all(const float* __restrict__ w3,
                                 const float* __restrict__ w5,
                                 const float* __restrict__ w7)
{
    int i = blockIdx.x * 256 + threadIdx.x;
    if (i < 9 * 4096) {
        g_wt[WT_B3 + i] = w3[(i & 4095) * 9 + (i >> 12)];
    } else if (i < (9 + 25) * 4096) {
        int j = i - 9 * 4096;
        g_wt[WT_B5 + j] = w5[(j & 4095) * 25 + (j >> 12)];
    } else if (i < (9 + 25 + 49) * 4096) {
        int j = i - (9 + 25) * 4096;
        g_wt[WT_B7 + j] = w7[(j & 4095) * 49 + (j >> 12)];
    }
}

// ---------------------------------------------------------------------------
// Sample body: 32 pixels/block, 128 threads, taps [kk0,kk1) only.
// Writes to outp with channel stride CS (192 for direct out, 64 for partials).
// ---------------------------------------------------------------------------
template<int K>
__device__ __forceinline__ void sample_body(
    int tile, const float* __restrict__ x, float* __restrict__ outp,
    int CS, int kk0, int kk1,
    int offbase, int mskbase, int wtbase,
    float* s_w, float* s_samp, float* s_py, float* s_px, float* s_m)
{
    constexpr int KK  = K * K;
    constexpr int PAD = K / 2;
    constexpr int WP  = 68;
    constexpr int SP  = 36;

    const float* offp = g_offF + offbase;
    const float* mskp = g_mskF + mskbase;
    const float* wtp  = g_wt  + wtbase;

    const int tid  = threadIdx.x;
    const int pix0 = tile * 32;
    const int b    = pix0 / IHW;
    const int rem0 = pix0 - b * IHW;

    const int o0 = tid & 15;
    const int pb = (tid >> 4) * 4;
    const int sp = tid & 31;
    const int sc = tid >> 5;

    u64 acc[4][2];
    #pragma unroll
    for (int q = 0; q < 4; q++) { acc[q][0] = 0ull; acc[q][1] = 0ull; }

    for (int kk = kk0; kk < kk1; kk++) {
        if (tid < 32) {
            int rem = rem0 + tid;
            int h = rem / IW, w = rem - h * IW;
            float oy = offp[(b * 2 * KK + 2 * kk    ) * IHW + rem];
            float ox = offp[(b * 2 * KK + 2 * kk + 1) * IHW + rem];
            s_py[tid] = (float)(h - PAD + kk / K) + oy;
            s_px[tid] = (float)(w - PAD + kk % K) + ox;
            s_m[tid]  = mskp[(b * KK + kk) * IHW + rem];
        }
        for (int i = tid; i < 4096; i += 128)
            s_w[(i >> 6) * WP + (i & 63)] = wtp[kk * 4096 + i];
        __syncthreads();

        {
            const float py = s_py[sp], px = s_px[sp], m = s_m[sp];
            const float y0f = floorf(py), x0f = floorf(px);
            const int   y0  = (int)y0f,   x0  = (int)x0f;
            const float wy1 = py - y0f, wx1 = px - x0f;
            const float wy0 = 1.f - wy1, wx0 = 1.f - wx1;
            const bool vy0 = (y0 >= 0) && (y0 < IH);
            const bool vy1 = (y0 + 1 >= 0) && (y0 + 1 < IH);
            const bool vx0 = (x0 >= 0) && (x0 < IW);
            const bool vx1 = (x0 + 1 >= 0) && (x0 + 1 < IW);
            const int y0c = min(max(y0, 0), IH - 1);
            const int y1c = min(max(y0 + 1, 0), IH - 1);
            const int x0c = min(max(x0, 0), IW - 1);
            const int x1c = min(max(x0 + 1, 0), IW - 1);
            const float w00 = wy0 * wx0 * ((vy0 && vx0) ? 1.f : 0.f) * m;
            const float w01 = wy0 * wx1 * ((vy0 && vx1) ? 1.f : 0.f) * m;
            const float w10 = wy1 * wx0 * ((vy1 && vx0) ? 1.f : 0.f) * m;
            const float w11 = wy1 * wx1 * ((vy1 && vx1) ? 1.f : 0.f) * m;
            const int i00 = y0c * IW + x0c, i01 = y0c * IW + x1c;
            const int i10 = y1c * IW + x0c, i11 = y1c * IW + x1c;
            const float* base = x + b * IC * IHW + sc * 16 * IHW;
            #pragma unroll
            for (int j = 0; j < 16; j++) {
                const float* xp = base + j * IHW;
                float v = w00 * xp[i00] + w01 * xp[i01]
                        + w10 * xp[i10] + w11 * xp[i11];
                s_samp[(sc * 16 + j) * SP + sp] = v;
            }
        }
        __syncthreads();

        #pragma unroll 4
        for (int c = 0; c < 64; c += 4) {
            const float4 wA = *(const float4*)&s_w[(o0     ) * WP + c];
            const float4 wB = *(const float4*)&s_w[(o0 + 16) * WP + c];
            const float4 wC = *(const float4*)&s_w[(o0 + 32) * WP + c];
            const float4 wD = *(const float4*)&s_w[(o0 + 48) * WP + c];
            const float4 sA = *(const float4*)&s_samp[(c + 0) * SP + pb];
            const float4 sB = *(const float4*)&s_samp[(c + 1) * SP + pb];
            const float4 sC = *(const float4*)&s_samp[(c + 2) * SP + pb];
            const float4 sD = *(const float4*)&s_samp[(c + 3) * SP + pb];
            const u64 sAl = pack2(sA.x, sA.y), sAh = pack2(sA.z, sA.w);
            const u64 sBl = pack2(sB.x, sB.y), sBh = pack2(sB.z, sB.w);
            const u64 sCl = pack2(sC.x, sC.y), sCh = pack2(sC.z, sC.w);
            const u64 sDl = pack2(sD.x, sD.y), sDh = pack2(sD.z, sD.w);
            #pragma unroll
            for (int q = 0; q < 4; q++) {
                const float4 w = (q == 0) ? wA : (q == 1) ? wB : (q == 2) ? wC : wD;
                u64 w0 = pack2(w.x, w.x);
                u64 w1 = pack2(w.y, w.y);
                u64 w2 = pack2(w.z, w.z);
                u64 w3 = pack2(w.w, w.w);
                ffma2(acc[q][0], w0, sAl); ffma2(acc[q][1], w0, sAh);
                ffma2(acc[q][0], w1, sBl); ffma2(acc[q][1], w1, sBh);
                ffma2(acc[q][0], w2, sCl); ffma2(acc[q][1], w2, sCh);
                ffma2(acc[q][0], w3, sDl); ffma2(acc[q][1], w3, sDh);
            }
        }
        __syncthreads();
    }

    #pragma unroll
    for (int q = 0; q < 4; q++) {
        float2 lo = unpack2(acc[q][0]);
        float2 hi = unpack2(acc[q][1]);
        const int oo = o0 + q * 16;
        s_samp[oo * SP + pb + 0] = lo.x;
        s_samp[oo * SP + pb + 1] = lo.y;
        s_samp[oo * SP + pb + 2] = hi.x;
        s_samp[oo * SP + pb + 3] = hi.y;
    }
    __syncthreads();
    for (int i = tid; i < 2048; i += 128) {
        const int oo = i >> 5, p = i & 31;
        outp[(b * CS + oo) * IHW + rem0 + p] = s_samp[oo * SP + p];
    }
}

// Balanced sampler: 2800 blocks = 400 tiles x 7 tap-chunk units, interleaved.
// unit 0: k3 [0,9) -> direct out; units 1-2: k5 chunks; units 3-6: k7 chunks.
__global__ void __launch_bounds__(128) sample_all(
    const float* __restrict__ x, float* __restrict__ out)
{
    __shared__ __align__(16) float s_w[64 * 68];
    __shared__ __align__(16) float s_samp[64 * 36];
    __shared__ float s_py[32], s_px[32], s_m[32];

    const int unit = blockIdx.x % 7;
    const int tile = blockIdx.x / 7;

    if (unit == 0) {
        sample_body<3>(tile, x, out, 192, 0, 9,
                       OFF_B3, MSK_B3, WT_B3, s_w, s_samp, s_py, s_px, s_m);
    } else if (unit <= 2) {
        const int c = unit - 1;
        const int k0 = c * 13, k1 = (c == 1) ? 25 : 13;
        sample_body<5>(tile, x, g_outP5 + (size_t)c * PCH, 64, k0, k1,
                       OFF_B5, MSK_B5, WT_B5, s_w, s_samp, s_py, s_px, s_m);
    } else {
        const int c = unit - 3;
        const int k0 = c * 13, k1 = (c == 3) ? 49 : (c + 1) * 13;
        sample_body<7>(tile, x, g_outP7 + (size_t)c * PCH, 64, k0, k1,
                       OFF_B7, MSK_B7, WT_B7, s_w, s_samp, s_py, s_px, s_m);
    }
}

// Fold k5/k7 partials into out channels [64,192)
__global__ void reduce_out(float* __restrict__ out)
{
    int i = blockIdx.x * 256 + threadIdx.x;
    if (i < PCH) {
        const int b     = i / (64 * IHW);
        const int local = i - b * 64 * IHW;
        out[(b * 192 + 64) * IHW + local]  = g_outP5[i] + g_outP5[PCH + i];
        out[(b * 192 + 128) * IHW + local] = g_outP7[i] + g_outP7[PCH + i]
                                           + g_outP7[2 * (size_t)PCH + i]
                                           + g_outP7[3 * (size_t)PCH + i];
    }
}

// ---------------------------------------------------------------------------
extern "C" void kernel_launch(void* const* d_in, const int* in_sizes, int n_in,
                              void* d_out, int out_size)
{
    const float* x = (const float*)d_in[0];
    float* out = (float*)d_out;

    conv_all<<<3400, 128>>>(x,
        (const float*)d_in[1],  (const float*)d_in[3],
        (const float*)d_in[6],  (const float*)d_in[8],
        (const float*)d_in[11], (const float*)d_in[13]);

    wt_transpose_all<<<(83 * 4096 + 255) / 256, 256>>>(
        (const float*)d_in[5], (const float*)d_in[10], (const float*)d_in[15]);

    reduce_offmask<<<(OFF_TOT + MSK_TOT + 255) / 256, 256>>>(
        (const float*)d_in[2],  (const float*)d_in[4],
        (const float*)d_in[7],  (const float*)d_in[9],
        (const float*)d_in[12], (const float*)d_in[14]);

    sample_all<<<2800, 128>>>(x, out);

    reduce_out<<<(PCH + 255) / 256, 256>>>(out);
}

// round 8
// speedup vs baseline: 1.9522x; 1.0668x over previous
#include <cuda_runtime.h>
#include <math.h>

constexpr int NB  = 2;
constexpr int IC  = 64;
constexpr int IH  = 80;
constexpr int IW  = 80;
constexpr int IHW = IH * IW;   // 6400
constexpr int NSPLIT  = 4;
constexpr int CICHUNK = IC / NSPLIT;   // 16

// Concatenated offset/mask layouts (branch bases)
constexpr int OFF_B3 = 0;
constexpr int OFF_B5 = NB * 18 * IHW;
constexpr int OFF_B7 = OFF_B5 + NB * 50 * IHW;
constexpr int OFF_TOT = OFF_B7 + NB * 98 * IHW;
constexpr int MSK_B3 = 0;
constexpr int MSK_B5 = NB * 9 * IHW;
constexpr int MSK_B7 = MSK_B5 + NB * 25 * IHW;
constexpr int MSK_TOT = MSK_B7 + NB * 49 * IHW;
constexpr int WT_B3 = 0;
constexpr int WT_B5 = 9 * 4096;
constexpr int WT_B7 = (9 + 25) * 4096;
constexpr int PCH   = NB * 64 * IHW;   // one partial-chunk slab

__device__ float g_offP[NSPLIT * OFF_TOT];
__device__ float g_mskP[NSPLIT * MSK_TOT];
__device__ float g_offF[OFF_TOT];
__device__ float g_mskF[MSK_TOT];
__device__ float g_wt[(9 + 25 + 49) * 4096];  // [kk][o*64+c]
__device__ float g_outP5[2 * PCH];
__device__ float g_outP7[4 * PCH];

// ---- f32x2 packed helpers (sm_103a) ----
using u64 = unsigned long long;
__device__ __forceinline__ u64 pack2(float a, float b) {
    u64 r; asm("mov.b64 %0, {%1, %2};" : "=l"(r) : "f"(a), "f"(b)); return r;
}
__device__ __forceinline__ void ffma2(u64& d, u64 a, u64 b) {
    asm("fma.rn.f32x2 %0, %1, %2, %3;" : "=l"(d) : "l"(a), "l"(b), "l"(d));
}
__device__ __forceinline__ float2 unpack2(u64 v) {
    float x, y; asm("mov.b64 {%0, %1}, %2;" : "=f"(x), "=f"(y) : "l"(v));
    return make_float2(x, y);
}

// ---------------------------------------------------------------------------
// Conv body: 16x16 spatial tile, 128 threads, 2 px x 16 co, split-K over ci.
// ---------------------------------------------------------------------------
template<int K, int NG>
__device__ __forceinline__ void conv_body(
    int lb, const float* __restrict__ x,
    const float* __restrict__ w_off, const float* __restrict__ w_msk,
    int offbase, int mskbase, float* sx, float* sw)
{
    constexpr int KK  = K * K;
    constexpr int PAD = K / 2;
    constexpr int CO_TOT = 3 * KK;
    constexpr int TS  = 16 + K - 1;
    constexpr int P   = TS | 1;

    const int s    = lb & 3;
    int r          = lb >> 2;
    const int tile = r % 25;  r /= 25;
    const int grp  = r % NG;
    const int b    = r / NG;

    const int tid = threadIdx.x;
    const int tx  = tid & 15;
    const int ty  = tid >> 4;
    const int bx0 = (tile % 5) * 16;
    const int by0 = (tile / 5) * 16;
    const int co0 = grp * 16;
    const int ci0 = s * CICHUNK;

    u64 acc0[8], acc1[8];
    #pragma unroll
    for (int i = 0; i < 8; i++) { acc0[i] = 0ull; acc1[i] = 0ull; }

    for (int ci = ci0; ci < ci0 + CICHUNK; ci++) {
        const float* xp = x + (b * IC + ci) * IHW;
        for (int i = tid; i < TS * TS; i += 128) {
            int ry = i / TS, rx = i - ry * TS;
            int gy = by0 - PAD + ry, gx = bx0 - PAD + rx;
            float v = 0.f;
            if (gy >= 0 && gy < IH && gx >= 0 && gx < IW) v = xp[gy * IW + gx];
            sx[ry * P + rx] = v;
        }
        for (int i = tid; i < 16 * KK; i += 128) {
            int lc = i / KK, tap = i - lc * KK;
            int co = co0 + lc;
            float v = 0.f;
            if (co < 2 * KK)       v = w_off[(co * IC + ci) * KK + tap];
            else if (co < CO_TOT)  v = w_msk[((co - 2 * KK) * IC + ci) * KK + tap];
            sw[tap * 16 + lc] = v;
        }
        __syncthreads();

        #pragma unroll
        for (int tap = 0; tap < KK; tap++) {
            const int dy = tap / K, dx = tap - dy * K;
            const float xv0 = sx[(ty + dy) * P + tx + dx];
            const float xv1 = sx[(ty + 8 + dy) * P + tx + dx];
            const u64 xp0 = pack2(xv0, xv0);
            const u64 xp1 = pack2(xv1, xv1);
            const u64* w2 = reinterpret_cast<const u64*>(&sw[tap * 16]);
            #pragma unroll
            for (int i = 0; i < 8; i++) {
                u64 w = w2[i];
                ffma2(acc0[i], xp0, w);
                ffma2(acc1[i], xp1, w);
            }
        }
        __syncthreads();
    }

    float* op = g_offP + (size_t)s * OFF_TOT + offbase;
    float* mp = g_mskP + (size_t)s * MSK_TOT + mskbase;
    const int oy = by0 + ty, ox = bx0 + tx;
    const int idx0 = oy * IW + ox;
    const int idx1 = (oy + 8) * IW + ox;
    #pragma unroll
    for (int i = 0; i < 8; i++) {
        float2 v0 = unpack2(acc0[i]);
        float2 v1 = unpack2(acc1[i]);
        #pragma unroll
        for (int h = 0; h < 2; h++) {
            const int co = co0 + 2 * i + h;
            const float a0 = h ? v0.y : v0.x;
            const float a1 = h ? v1.y : v1.x;
            if (co < 2 * KK) {
                op[(b * 2 * KK + co) * IHW + idx0] = a0;
                op[(b * 2 * KK + co) * IHW + idx1] = a1;
            } else if (co < CO_TOT) {
                const int cm = co - 2 * KK;
                mp[(b * KK + cm) * IHW + idx0] = a0;
                mp[(b * KK + cm) * IHW + idx1] = a1;
            }
        }
    }
}

// Merged conv: blocks [0,400)=k3, [400,1400)=k5, [1400,3400)=k7
__global__ void __launch_bounds__(128) conv_all(
    const float* __restrict__ x,
    const float* __restrict__ w3o, const float* __restrict__ w3m,
    const float* __restrict__ w5o, const float* __restrict__ w5m,
    const float* __restrict__ w7o, const float* __restrict__ w7m)
{
    __shared__ __align__(16) float sx[22 * 23];
    __shared__ __align__(16) float sw[49 * 16];

    const int bid = blockIdx.x;
    if (bid < 400)        conv_body<3, 2>(bid,        x, w3o, w3m, OFF_B3, MSK_B3, sx, sw);
    else if (bid < 1400)  conv_body<5, 5>(bid - 400,  x, w5o, w5m, OFF_B5, MSK_B5, sx, sw);
    else                  conv_body<7,10>(bid - 1400, x, w7o, w7m, OFF_B7, MSK_B7, sx, sw);
}

// ---------------------------------------------------------------------------
// Reduce conv partials: offsets += bias; masks = sigmoid(sum + bias)
// ---------------------------------------------------------------------------
__global__ void reduce_offmask(
    const float* __restrict__ b3o, const float* __restrict__ b3m,
    const float* __restrict__ b5o, const float* __restrict__ b5m,
    const float* __restrict__ b7o, const float* __restrict__ b7m)
{
    int i = blockIdx.x * 256 + threadIdx.x;
    if (i < OFF_TOT) {
        float v = g_offP[i] + g_offP[OFF_TOT + i]
                + g_offP[2 * OFF_TOT + i] + g_offP[3 * (size_t)OFF_TOT + i];
        const float* bp; int local, kk2;
        if (i < OFF_B5)      { bp = b3o; local = i;          kk2 = 18; }
        else if (i < OFF_B7) { bp = b5o; local = i - OFF_B5; kk2 = 50; }
        else                 { bp = b7o; local = i - OFF_B7; kk2 = 98; }
        int co = (local / IHW) % kk2;
        g_offF[i] = v + bp[co];
    } else {
        int j = i - OFF_TOT;
        if (j < MSK_TOT) {
            float v = g_mskP[j] + g_mskP[MSK_TOT + j]
                    + g_mskP[2 * MSK_TOT + j] + g_mskP[3 * (size_t)MSK_TOT + j];
            const float* bp; int local, kk;
            if (j < MSK_B5)      { bp = b3m; local = j;          kk = 9;  }
            else if (j < MSK_B7) { bp = b5m; local = j - MSK_B5; kk = 25; }
            else                 { bp = b7m; local = j - MSK_B7; kk = 49; }
            int cm = (local / IHW) % kk;
            g_mskF[j] = 1.f / (1.f + expf(-(v + bp[cm])));
        }
    }
}

// ---------------------------------------------------------------------------
// Weight transpose: w_dcn[o][c][kk] -> g_wt[base + kk*4096 + o*64 + c]
// ---------------------------------------------------------------------------
__global__ void wt_transpose_all(const float* __restrict__ w3,
                                 const float* __restrict__ w5,
                                 const float* __restrict__ w7)
{
    int i = blockIdx.x * 256 + threadIdx.x;
    if (i < 9 * 4096) {
        g_wt[WT_B3 + i] = w3[(i & 4095) * 9 + (i >> 12)];
    } else if (i < (9 + 25) * 4096) {
        int j = i - 9 * 4096;
        g_wt[WT_B5 + j] = w5[(j & 4095) * 25 + (j >> 12)];
    } else if (i < (9 + 25 + 49) * 4096) {
        int j = i - (9 + 25) * 4096;
        g_wt[WT_B7 + j] = w7[(j & 4095) * 49 + (j >> 12)];
    }
}

// ---------------------------------------------------------------------------
// Sample body: 64 pixels/block, 128 threads, taps [kk0,kk1).
// Gather: thread = 1 pixel x 32 channels. Matvec: thread = 4 o x 8 px.
// ---------------------------------------------------------------------------
template<int K>
__device__ __forceinline__ void sample_body(
    int tile, const float* __restrict__ x, float* __restrict__ outp,
    int CS, int kk0, int kk1,
    int offbase, int mskbase, int wtbase,
    float* s_w, float* s_samp, float* s_py, float* s_px, float* s_m)
{
    constexpr int KK  = K * K;
    constexpr int PAD = K / 2;
    constexpr int WP  = 68;   // s_w pitch [o][c]
    constexpr int SP  = 68;   // s_samp pitch [c][p] (64 px + 4 pad)

    const float* offp = g_offF + offbase;
    const float* mskp = g_mskF + mskbase;
    const float* wtp  = g_wt  + wtbase;

    const int tid  = threadIdx.x;
    const int pix0 = tile * 64;
    const int b    = pix0 / IHW;
    const int rem0 = pix0 - b * IHW;

    const int o0 = tid & 15;         // matvec o rows: o0, +16, +32, +48
    const int pb = (tid >> 4) * 8;   // matvec pixel base (8 px per thread)
    const int sp = tid & 63;         // sampling pixel
    const int sc = tid >> 6;         // sampling channel half (0/1, 32 ch each)

    u64 acc[4][4];
    #pragma unroll
    for (int q = 0; q < 4; q++)
        #pragma unroll
        for (int j = 0; j < 4; j++) acc[q][j] = 0ull;

    for (int kk = kk0; kk < kk1; kk++) {
        if (tid < 64) {
            int rem = rem0 + tid;
            int h = rem / IW, w = rem - h * IW;
            float oy = offp[(b * 2 * KK + 2 * kk    ) * IHW + rem];
            float ox = offp[(b * 2 * KK + 2 * kk + 1) * IHW + rem];
            s_py[tid] = (float)(h - PAD + kk / K) + oy;
            s_px[tid] = (float)(w - PAD + kk % K) + ox;
            s_m[tid]  = mskp[(b * KK + kk) * IHW + rem];
        }
        for (int i = tid; i < 4096; i += 128)
            s_w[(i >> 6) * WP + (i & 63)] = wtp[kk * 4096 + i];
        __syncthreads();

        // bilinear gather: pixel sp, 32 channels (sc*32 .. +31)
        {
            const float py = s_py[sp], px = s_px[sp], m = s_m[sp];
            const float y0f = floorf(py), x0f = floorf(px);
            const int   y0  = (int)y0f,   x0  = (int)x0f;
            const float wy1 = py - y0f, wx1 = px - x0f;
            const float wy0 = 1.f - wy1, wx0 = 1.f - wx1;
            const bool vy0 = (y0 >= 0) && (y0 < IH);
            const bool vy1 = (y0 + 1 >= 0) && (y0 + 1 < IH);
            const bool vx0 = (x0 >= 0) && (x0 < IW);
            const bool vx1 = (x0 + 1 >= 0) && (x0 + 1 < IW);
            const int y0c = min(max(y0, 0), IH - 1);
            const int y1c = min(max(y0 + 1, 0), IH - 1);
            const int x0c = min(max(x0, 0), IW - 1);
            const int x1c = min(max(x0 + 1, 0), IW - 1);
            const float w00 = wy0 * wx0 * ((vy0 && vx0) ? 1.f : 0.f) * m;
            const float w01 = wy0 * wx1 * ((vy0 && vx1) ? 1.f : 0.f) * m;
            const float w10 = wy1 * wx0 * ((vy1 && vx0) ? 1.f : 0.f) * m;
            const float w11 = wy1 * wx1 * ((vy1 && vx1) ? 1.f : 0.f) * m;
            const int i00 = y0c * IW + x0c, i01 = y0c * IW + x1c;
            const int i10 = y1c * IW + x0c, i11 = y1c * IW + x1c;
            const float* base = x + (b * IC + sc * 32) * IHW;
            #pragma unroll
            for (int j = 0; j < 32; j++) {
                const float* xp = base + j * IHW;
                float v = w00 * xp[i00] + w01 * xp[i01]
                        + w10 * xp[i10] + w11 * xp[i11];
                s_samp[(sc * 32 + j) * SP + sp] = v;
            }
        }
        __syncthreads();

        // matvec: 4 o x 8 px per thread, f32x2 over pixel pairs
        #pragma unroll 2
        for (int c0 = 0; c0 < 64; c0 += 4) {
            float4 w[4];
            w[0] = *(const float4*)&s_w[(o0     ) * WP + c0];
            w[1] = *(const float4*)&s_w[(o0 + 16) * WP + c0];
            w[2] = *(const float4*)&s_w[(o0 + 32) * WP + c0];
            w[3] = *(const float4*)&s_w[(o0 + 48) * WP + c0];
            #pragma unroll
            for (int cc = 0; cc < 4; cc++) {
                const float4 sA = *(const float4*)&s_samp[(c0 + cc) * SP + pb];
                const float4 sB = *(const float4*)&s_samp[(c0 + cc) * SP + pb + 4];
                const u64 sl0 = pack2(sA.x, sA.y);
                const u64 sl1 = pack2(sA.z, sA.w);
                const u64 sl2 = pack2(sB.x, sB.y);
                const u64 sl3 = pack2(sB.z, sB.w);
                #pragma unroll
                for (int q = 0; q < 4; q++) {
                    const float wv = ((const float*)&w[q])[cc];
                    const u64 wp = pack2(wv, wv);
                    ffma2(acc[q][0], wp, sl0);
                    ffma2(acc[q][1], wp, sl1);
                    ffma2(acc[q][2], wp, sl2);
                    ffma2(acc[q][3], wp, sl3);
                }
            }
        }
        __syncthreads();
    }

    // stage to smem for coalesced output stores
    #pragma unroll
    for (int q = 0; q < 4; q++) {
        const int oo = o0 + q * 16;
        #pragma unroll
        for (int j = 0; j < 4; j++) {
            float2 v = unpack2(acc[q][j]);
            s_samp[oo * SP + pb + 2 * j]     = v.x;
            s_samp[oo * SP + pb + 2 * j + 1] = v.y;
        }
    }
    __syncthreads();
    for (int i = tid; i < 4096; i += 128) {
        const int oo = i >> 6, p = i & 63;
        outp[(b * CS + oo) * IHW + rem0 + p] = s_samp[oo * SP + p];
    }
}

// Balanced sampler: 1400 blocks = 200 tiles x 7 tap-chunk units, interleaved.
__global__ void __launch_bounds__(128) sample_all(
    const float* __restrict__ x, float* __restrict__ out)
{
    __shared__ __align__(16) float s_w[64 * 68];
    __shared__ __align__(16) float s_samp[64 * 68];
    __shared__ float s_py[64], s_px[64], s_m[64];

    const int unit = blockIdx.x % 7;
    const int tile = blockIdx.x / 7;

    if (unit == 0) {
        sample_body<3>(tile, x, out, 192, 0, 9,
                       OFF_B3, MSK_B3, WT_B3, s_w, s_samp, s_py, s_px, s_m);
    } else if (unit <= 2) {
        const int c = unit - 1;
        const int k0 = c * 13, k1 = (c == 1) ? 25 : 13;
        sample_body<5>(tile, x, g_outP5 + (size_t)c * PCH, 64, k0, k1,
                       OFF_B5, MSK_B5, WT_B5, s_w, s_samp, s_py, s_px, s_m);
    } else {
        const int c = unit - 3;
        const int k0 = c * 13, k1 = (c == 3) ? 49 : (c + 1) * 13;
        sample_body<7>(tile, x, g_outP7 + (size_t)c * PCH, 64, k0, k1,
                       OFF_B7, MSK_B7, WT_B7, s_w, s_samp, s_py, s_px, s_m);
    }
}

// Fold k5/k7 partials into out channels [64,192)
__global__ void reduce_out(float* __restrict__ out)
{
    int i = blockIdx.x * 256 + threadIdx.x;
    if (i < PCH) {
        const int b     = i / (64 * IHW);
        const int local = i - b * 64 * IHW;
        out[(b * 192 + 64) * IHW + local]  = g_outP5[i] + g_outP5[PCH + i];
        out[(b * 192 + 128) * IHW + local] = g_outP7[i] + g_outP7[PCH + i]
                                           + g_outP7[2 * (size_t)PCH + i]
                                           + g_outP7[3 * (size_t)PCH + i];
    }
}

// ---------------------------------------------------------------------------
extern "C" void kernel_launch(void* const* d_in, const int* in_sizes, int n_in,
                              void* d_out, int out_size)
{
    const float* x = (const float*)d_in[0];
    float* out = (float*)d_out;

    conv_all<<<3400, 128>>>(x,
        (const float*)d_in[1],  (const float*)d_in[3],
        (const float*)d_in[6],  (const float*)d_in[8],
        (const float*)d_in[11], (const float*)d_in[13]);

    wt_transpose_all<<<(83 * 4096 + 255) / 256, 256>>>(
        (const float*)d_in[5], (const float*)d_in[10], (const float*)d_in[15]);

    reduce_offmask<<<(OFF_TOT + MSK_TOT + 255) / 256, 256>>>(
        (const float*)d_in[2],  (const float*)d_in[4],
        (const float*)d_in[7],  (const float*)d_in[9],
        (const float*)d_in[12], (const float*)d_in[14]);

    sample_all<<<1400, 128>>>(x, out);

    reduce_out<<<(PCH + 255) / 256, 256>>>(out);
}